// round 14
// baseline (speedup 1.0000x reference)
#include <cuda_runtime.h>
#include <cuda_fp16.h>
#include <cstdint>

#define N_NODES   50000
#define N_EDGES   600000
#define HID       128
#define N_GRAPHS  128
#define N_CLASSES 10

#define SCAN_B    512
#define SCAN_NB   ((N_NODES + SCAN_B - 1) / SCAN_B)    // 98

// ---------------- scratch (no allocation allowed) ----------------
__device__ __half g_aggH[(size_t)N_NODES * HID];  // fp16 GEMM input (activations)
__device__ __half g_hbA [(size_t)N_NODES * HID];  // fp16 messages, ping
__device__ __half g_hbB [(size_t)N_NODES * HID];  // fp16 messages, pong
__device__ float g_dinv[N_NODES];
__device__ int   g_deg [N_NODES];
__device__ int   g_cur [N_NODES];
__device__ int   g_rowptr[N_NODES + 1];
__device__ int   g_csr_src[N_EDGES];
__device__ int   g_bsum[SCAN_NB];
__device__ float g_pool[N_GRAPHS * HID];
__device__ float g_cnt [N_GRAPHS];
// W in mma.sync B-fragment layout, f16 hi/lo: [layer][term][kstep][ntile][lane]
__device__ uint2 g_Bfrag[6][2][8][16][32];

// ---------------- setup kernels ----------------
__global__ void zero_kernel() {
    int i = blockIdx.x * blockDim.x + threadIdx.x;
    if (i < N_NODES)      { g_deg[i] = 0; g_cur[i] = 0; }
    if (i < N_GRAPHS * HID) g_pool[i] = 0.f;
    if (i < N_GRAPHS)       g_cnt[i] = 0.f;
}

__global__ void deg_kernel(const int* __restrict__ ei) {
    int e = blockIdx.x * blockDim.x + threadIdx.x;
    if (e < N_EDGES) atomicAdd(&g_deg[ei[N_EDGES + e]], 1);
}

// dinv + graph node counts in one pass
__global__ void dinv_kernel(const int* __restrict__ batch) {
    int i = blockIdx.x * blockDim.x + threadIdx.x;
    if (i < N_NODES) {
        g_dinv[i] = rsqrtf((float)g_deg[i] + 1.0f);
        atomicAdd(&g_cnt[batch[i]], 1.f);
    }
}

// Build f16 hi/lo B fragments for all 6 layers in one launch.
struct WPtrs { const float* p[6]; };
__global__ void wprep_kernel(WPtrs wp) {
    int t = blockIdx.x * blockDim.x + threadIdx.x;   // 0..24575
    if (t >= 6 * 8 * 16 * 32) return;
    int l    = t >> 12;
    int s    = (t >> 9) & 7;
    int j    = (t >> 5) & 15;
    int lane = t & 31;
    const float* W = wp.p[l];
    int k0 = s * 16 + (lane & 3) * 2;
    int nn = j * 8 + (lane >> 2);
    unsigned hw[2], lw[2];
    #pragma unroll
    for (int q = 0; q < 2; q++) {
        float w0 = W[(k0 + q * 8)     * 128 + nn];
        float w1 = W[(k0 + q * 8 + 1) * 128 + nn];
        __half h0 = __float2half_rn(w0);
        __half h1 = __float2half_rn(w1);
        __half l0 = __float2half_rn(w0 - __half2float(h0));
        __half l1 = __float2half_rn(w1 - __half2float(h1));
        hw[q] = (unsigned)__half_as_ushort(h0)
              | ((unsigned)__half_as_ushort(h1) << 16);
        lw[q] = (unsigned)__half_as_ushort(l0)
              | ((unsigned)__half_as_ushort(l1) << 16);
    }
    g_Bfrag[l][0][s][j][lane] = make_uint2(hw[0], hw[1]);
    g_Bfrag[l][1][s][j][lane] = make_uint2(lw[0], lw[1]);
}

// ---- decoupled scan ----
__global__ __launch_bounds__(SCAN_B) void scan1_kernel() {
    __shared__ int s[SCAN_B];
    int i = blockIdx.x * SCAN_B + threadIdx.x;
    int v = (i < N_NODES) ? g_deg[i] : 0;
    s[threadIdx.x] = v;
    __syncthreads();
    #pragma unroll
    for (int off = 1; off < SCAN_B; off <<= 1) {
        int t = (threadIdx.x >= off) ? s[threadIdx.x - off] : 0;
        __syncthreads();
        s[threadIdx.x] += t;
        __syncthreads();
    }
    if (i < N_NODES) g_rowptr[i + 1] = s[threadIdx.x];
    if (threadIdx.x == SCAN_B - 1) g_bsum[blockIdx.x] = s[SCAN_B - 1];
}

__global__ void scan2_kernel() {
    __shared__ int s[128];
    int v = (threadIdx.x < SCAN_NB) ? g_bsum[threadIdx.x] : 0;
    s[threadIdx.x] = v;
    __syncthreads();
    #pragma unroll
    for (int off = 1; off < 128; off <<= 1) {
        int t = (threadIdx.x >= off) ? s[threadIdx.x - off] : 0;
        __syncthreads();
        s[threadIdx.x] += t;
        __syncthreads();
    }
    if (threadIdx.x < SCAN_NB) g_bsum[threadIdx.x] = s[threadIdx.x] - v;
}

__global__ void scan3_kernel() {
    int i = blockIdx.x * blockDim.x + threadIdx.x;
    if (i == 0) g_rowptr[0] = 0;
    if (i < N_NODES) g_rowptr[i + 1] += g_bsum[i / SCAN_B];
}

__global__ void place_kernel(const int* __restrict__ ei) {
    int e = blockIdx.x * blockDim.x + threadIdx.x;
    if (e >= N_EDGES) return;
    int r = ei[e];
    int c = ei[N_EDGES + e];
    int pos = g_rowptr[c] + atomicAdd(&g_cur[c], 1);
    g_csr_src[pos] = r;
}

// ---------------- gather: msgs -> relu(dinv*sum + bias) -> fp16 agg ------
__device__ __forceinline__ float4 h4_to_f4(uint2 u) {
    __half2 a = *(__half2*)&u.x;
    __half2 b = *(__half2*)&u.y;
    float2 fa = __half22float2(a);
    float2 fb = __half22float2(b);
    return make_float4(fa.x, fa.y, fb.x, fb.y);
}

__global__ __launch_bounds__(256) void gather_kernel(
    int layer, const float* __restrict__ bias)
{
    int gt   = blockIdx.x * blockDim.x + threadIdx.x;
    int node = gt >> 5;
    int lane = gt & 31;
    if (node >= N_NODES) return;

    const uint2* hb2 = (const uint2*)((layer & 1) ? g_hbA : g_hbB);
    float4 acc  = h4_to_f4(hb2[(size_t)node * 32 + lane]);   // self-loop
    float4 acc2 = make_float4(0.f, 0.f, 0.f, 0.f);
    int j  = g_rowptr[node];
    int e1 = g_rowptr[node + 1];

    for (; j + 8 <= e1; j += 8) {
        int s0 = g_csr_src[j];
        int s1 = g_csr_src[j + 1];
        int s2 = g_csr_src[j + 2];
        int s3 = g_csr_src[j + 3];
        int s4 = g_csr_src[j + 4];
        int s5 = g_csr_src[j + 5];
        int s6 = g_csr_src[j + 6];
        int s7 = g_csr_src[j + 7];
        float4 v0 = h4_to_f4(hb2[(size_t)s0 * 32 + lane]);
        float4 v1 = h4_to_f4(hb2[(size_t)s1 * 32 + lane]);
        float4 v2 = h4_to_f4(hb2[(size_t)s2 * 32 + lane]);
        float4 v3 = h4_to_f4(hb2[(size_t)s3 * 32 + lane]);
        float4 v4 = h4_to_f4(hb2[(size_t)s4 * 32 + lane]);
        float4 v5 = h4_to_f4(hb2[(size_t)s5 * 32 + lane]);
        float4 v6 = h4_to_f4(hb2[(size_t)s6 * 32 + lane]);
        float4 v7 = h4_to_f4(hb2[(size_t)s7 * 32 + lane]);
        acc.x  += (v0.x + v1.x) + (v2.x + v3.x);
        acc.y  += (v0.y + v1.y) + (v2.y + v3.y);
        acc.z  += (v0.z + v1.z) + (v2.z + v3.z);
        acc.w  += (v0.w + v1.w) + (v2.w + v3.w);
        acc2.x += (v4.x + v5.x) + (v6.x + v7.x);
        acc2.y += (v4.y + v5.y) + (v6.y + v7.y);
        acc2.z += (v4.z + v5.z) + (v6.z + v7.z);
        acc2.w += (v4.w + v5.w) + (v6.w + v7.w);
    }
    if (j + 4 <= e1) {
        int s0 = g_csr_src[j];
        int s1 = g_csr_src[j + 1];
        int s2 = g_csr_src[j + 2];
        int s3 = g_csr_src[j + 3];
        float4 v0 = h4_to_f4(hb2[(size_t)s0 * 32 + lane]);
        float4 v1 = h4_to_f4(hb2[(size_t)s1 * 32 + lane]);
        float4 v2 = h4_to_f4(hb2[(size_t)s2 * 32 + lane]);
        float4 v3 = h4_to_f4(hb2[(size_t)s3 * 32 + lane]);
        acc.x += (v0.x + v1.x) + (v2.x + v3.x);
        acc.y += (v0.y + v1.y) + (v2.y + v3.y);
        acc.z += (v0.z + v1.z) + (v2.z + v3.z);
        acc.w += (v0.w + v1.w) + (v2.w + v3.w);
        j += 4;
    }
    for (; j < e1; j++) {
        float4 v = h4_to_f4(hb2[(size_t)g_csr_src[j] * 32 + lane]);
        acc.x += v.x; acc.y += v.y; acc.z += v.z; acc.w += v.w;
    }
    acc.x += acc2.x; acc.y += acc2.y; acc.z += acc2.z; acc.w += acc2.w;
    float d = g_dinv[node];
    float4 pb = ((const float4*)bias)[lane];
    float4 a;
    a.x = fmaxf(fmaf(acc.x, d, pb.x), 0.f);
    a.y = fmaxf(fmaf(acc.y, d, pb.y), 0.f);
    a.z = fmaxf(fmaf(acc.z, d, pb.z), 0.f);
    a.w = fmaxf(fmaf(acc.w, d, pb.w), 0.f);
    __half2 o0 = __float22half2_rn(make_float2(a.x, a.y));
    __half2 o1 = __float22half2_rn(make_float2(a.z, a.w));
    uint2 o;
    o.x = *(unsigned*)&o0;
    o.y = *(unsigned*)&o1;
    ((uint2*)g_aggH)[(size_t)node * 32 + lane] = o;
}

// ---------------- mma.sync GEMM: 2-term f16 (A exact, W hi/lo) ----------
// X != null    : layer-0 prologue converts fp32 x -> f16 in-flight
// outFp16 == 1 : conv epilogue -> hbOut = half(c * dinv)
// outFp16 == 0 : FC epilogue  -> relu(c + postBias) pooled by batch into
//                g_pool (smem-staged, one global atomic per (graph,col)/block)
__device__ __forceinline__ void mma_f16(float* d, const unsigned* a,
                                        const unsigned* b) {
    asm("mma.sync.aligned.m16n8k16.row.col.f32.f16.f16.f32 "
        "{%0,%1,%2,%3}, {%4,%5,%6,%7}, {%8,%9}, {%0,%1,%2,%3};"
        : "+f"(d[0]), "+f"(d[1]), "+f"(d[2]), "+f"(d[3])
        : "r"(a[0]), "r"(a[1]), "r"(a[2]), "r"(a[3]), "r"(b[0]), "r"(b[1]));
}

#define A_LD    136                          // padded f16 row stride
#define TC_SMEM (128 * A_LD * 2)             // 34816 B (8704 floats)
#define MAX_SPAN 68                          // pool staging capacity (floats/128)

__global__ __launch_bounds__(256, 2) void gemm_kernel(
    const float* __restrict__ X, int layer, int n,
    const float* __restrict__ postBias, const int* __restrict__ batch,
    int outFp16)
{
    extern __shared__ char smem[];
    __half* aS = (__half*)smem;

    __half* hbOut = (layer & 1) ? g_hbB : g_hbA;

    int tid  = threadIdx.x;
    int lane = tid & 31;
    int wid  = tid >> 5;
    int row0 = blockIdx.x * 128;

    // A tile
    if (X) {
        // layer 0: fp32 x -> f16 convert in-flight
        #pragma unroll
        for (int it = 0; it < 32; it++) {
            int j = tid + it * 256;          // pair index 0..8191
            int r = j >> 6;
            int c = (j & 63) * 2;
            int row = row0 + r;
            float2 v = make_float2(0.f, 0.f);
            if (row < n) v = *(const float2*)&X[(size_t)row * HID + c];
            __half2 h = __float22half2_rn(v);
            *(unsigned*)&aS[r * A_LD + c] = *(unsigned*)&h;
        }
    } else {
        const uint4* src = (const uint4*)g_aggH;
        #pragma unroll
        for (int it = 0; it < 8; it++) {
            int j = tid + it * 256;          // 0..2047
            int r = j >> 4;
            int q = j & 15;
            int row = row0 + r;
            uint4 v = make_uint4(0u, 0u, 0u, 0u);
            if (row < n) v = src[(size_t)row * 16 + q];
            *(uint4*)&aS[r * A_LD + q * 8] = v;
        }
    }
    __syncthreads();

    // mma mainloop
    int wm = wid & 3;
    int wn = wid >> 2;
    int rA = wm * 32 + (lane >> 2);
    int cGrp = (lane & 3) * 2;

    float acc[2][8][4];
    #pragma unroll
    for (int i = 0; i < 2; i++)
        #pragma unroll
        for (int j = 0; j < 8; j++)
            #pragma unroll
            for (int q = 0; q < 4; q++) acc[i][j][q] = 0.f;

    const uint2* bfragHi = &g_Bfrag[layer][0][0][0][0];
    const uint2* bfragLo = &g_Bfrag[layer][1][0][0][0];

    #pragma unroll
    for (int s = 0; s < 8; s++) {
        int kc = s * 16 + cGrp;
        unsigned a[2][4];
        #pragma unroll
        for (int i = 0; i < 2; i++) {
            int r = rA + i * 16;
            a[i][0] = *(const unsigned*)&aS[(r    ) * A_LD + kc    ];
            a[i][1] = *(const unsigned*)&aS[(r + 8) * A_LD + kc    ];
            a[i][2] = *(const unsigned*)&aS[(r    ) * A_LD + kc + 8];
            a[i][3] = *(const unsigned*)&aS[(r + 8) * A_LD + kc + 8];
        }
        #pragma unroll
        for (int j = 0; j < 8; j++) {
            int nt = wn * 8 + j;
            uint2 bh = bfragHi[(s * 16 + nt) * 32 + lane];
            uint2 bl = bfragLo[(s * 16 + nt) * 32 + lane];
            #pragma unroll
            for (int i = 0; i < 2; i++) {
                mma_f16(acc[i][j], a[i], (const unsigned*)&bh);
                mma_f16(acc[i][j], a[i], (const unsigned*)&bl);
            }
        }
    }

    // ---- epilogue ----
    if (outFp16) {
        #pragma unroll
        for (int i = 0; i < 2; i++) {
            int r0 = row0 + rA + i * 16;
            int r1 = r0 + 8;
            bool ok0 = r0 < n, ok1 = r1 < n;
            float d0s = ok0 ? g_dinv[r0] : 0.f;
            float d1s = ok1 ? g_dinv[r1] : 0.f;
            #pragma unroll
            for (int j = 0; j < 8; j++) {
                int col = wn * 64 + j * 8 + cGrp;
                if (ok0) {
                    __half2 o = __float22half2_rn(
                        make_float2(acc[i][j][0] * d0s, acc[i][j][1] * d0s));
                    *(__half2*)&hbOut[(size_t)r0 * HID + col] = o;
                }
                if (ok1) {
                    __half2 o = __float22half2_rn(
                        make_float2(acc[i][j][2] * d1s, acc[i][j][3] * d1s));
                    *(__half2*)&hbOut[(size_t)r1 * HID + col] = o;
                }
            }
        }
    } else {
        // FC layer: relu(c + postBias), pooled by graph into g_pool.
        // rows owned by this thread (tile-local): rA, rA+8, rA+16, rA+24
        // acc map: acc[i][j][0/1] -> row rA+16i ; acc[i][j][2/3] -> row rA+16i+8
        __syncthreads();                       // done with aS
        float* sp = (float*)smem;

        int rlast = min(row0 + 127, n - 1);
        int g0   = batch[row0];
        int span = batch[rlast] - g0 + 1;      // sorted batch

        bool useSmem = (span <= MAX_SPAN);
        if (useSmem) {
            for (int i2 = tid; i2 < span * 128; i2 += 256) sp[i2] = 0.f;
        }
        __syncthreads();

        int rloc[4] = {rA, rA + 8, rA + 16, rA + 24};
        int gl[4];
        #pragma unroll
        for (int k = 0; k < 4; k++) {
            int rr = row0 + rloc[k];
            gl[k] = (rr < n) ? (batch[rr] - g0) : -1;
        }

        if (useSmem && gl[0] >= 0 && gl[0] == gl[1] && gl[0] == gl[2]
            && gl[0] == gl[3]) {
            // common case: all 4 rows in same graph -> column sums
            float* dst = sp + gl[0] * 128;
            #pragma unroll
            for (int j = 0; j < 8; j++) {
                int col = wn * 64 + j * 8 + cGrp;
                float b0 = postBias[col], b1 = postBias[col + 1];
                float s0 = fmaxf(acc[0][j][0] + b0, 0.f)
                         + fmaxf(acc[0][j][2] + b0, 0.f)
                         + fmaxf(acc[1][j][0] + b0, 0.f)
                         + fmaxf(acc[1][j][2] + b0, 0.f);
                float s1 = fmaxf(acc[0][j][1] + b1, 0.f)
                         + fmaxf(acc[0][j][3] + b1, 0.f)
                         + fmaxf(acc[1][j][1] + b1, 0.f)
                         + fmaxf(acc[1][j][3] + b1, 0.f);
                atomicAdd(dst + col,     s0);
                atomicAdd(dst + col + 1, s1);
            }
        } else {
            // boundary / fallback: per-row adds
            #pragma unroll
            for (int k = 0; k < 4; k++) {
                if (gl[k] < 0) continue;
                int i  = k >> 1;
                int qb = (k & 1) * 2;
                #pragma unroll
                for (int j = 0; j < 8; j++) {
                    int col = wn * 64 + j * 8 + cGrp;
                    float v0 = fmaxf(acc[i][j][qb]     + postBias[col],     0.f);
                    float v1 = fmaxf(acc[i][j][qb + 1] + postBias[col + 1], 0.f);
                    if (useSmem) {
                        atomicAdd(sp + gl[k] * 128 + col,     v0);
                        atomicAdd(sp + gl[k] * 128 + col + 1, v1);
                    } else {
                        atomicAdd(&g_pool[(g0 + gl[k]) * 128 + col],     v0);
                        atomicAdd(&g_pool[(g0 + gl[k]) * 128 + col + 1], v1);
                    }
                }
            }
        }
        __syncthreads();
        if (useSmem) {
            for (int i2 = tid; i2 < span * 128; i2 += 256) {
                float v = sp[i2];
                if (v != 0.f)
                    atomicAdd(&g_pool[(g0 + (i2 >> 7)) * 128 + (i2 & 127)], v);
            }
        }
    }
}

// ---------------- final head: mean, embeddings out, logits ----------------
__global__ void final_kernel(const float* __restrict__ Wlin,
                             const float* __restrict__ blin,
                             float* __restrict__ out) {
    int g = blockIdx.x;
    int t = threadIdx.x;
    __shared__ float p[HID];
    float c = fmaxf(g_cnt[g], 1.0f);
    float v = g_pool[g * HID + t] / c;
    out[N_GRAPHS * N_CLASSES + g * HID + t] = v;
    p[t] = v;
    __syncthreads();
    if (t < N_CLASSES) {
        float s = blin[t];
        #pragma unroll 8
        for (int j = 0; j < HID; j++) s += p[j] * Wlin[j * N_CLASSES + t];
        out[g * N_CLASSES + t] = s;
    }
}

// ---------------- launch ----------------
extern "C" void kernel_launch(void* const* d_in, const int* in_sizes, int n_in,
                              void* d_out, int out_size)
{
    const float* x     = (const float*)d_in[0];
    const int*   ei    = (const int*)d_in[1];      // int32 (JAX x64 disabled)
    const int*   batch = (const int*)d_in[2];
    const float* W[6] = {(const float*)d_in[3],  (const float*)d_in[5],
                         (const float*)d_in[7],  (const float*)d_in[9],
                         (const float*)d_in[11], (const float*)d_in[13]};
    const float* b[6] = {(const float*)d_in[4],  (const float*)d_in[6],
                         (const float*)d_in[8],  (const float*)d_in[10],
                         (const float*)d_in[12], (const float*)d_in[14]};
    const float* Wlin = (const float*)d_in[15];
    const float* blin = (const float*)d_in[16];
    float* out = (float*)d_out;

    cudaFuncSetAttribute(gemm_kernel,
                         cudaFuncAttributeMaxDynamicSharedMemorySize, TC_SMEM);

    zero_kernel <<<(N_NODES + 255) / 256, 256>>>();
    deg_kernel  <<<(N_EDGES + 255) / 256, 256>>>(ei);
    dinv_kernel <<<(N_NODES + 255) / 256, 256>>>(batch);
    scan1_kernel<<<SCAN_NB, SCAN_B>>>();
    scan2_kernel<<<1, 128>>>();
    scan3_kernel<<<(N_NODES + 255) / 256, 256>>>();
    place_kernel<<<(N_EDGES + 255) / 256, 256>>>(ei);
    WPtrs wp;
    for (int l = 0; l < 6; l++) wp.p[l] = W[l];
    wprep_kernel<<<96, 256>>>(wp);

    const int gemm_grid   = (N_NODES + 127) / 128;        // 391
    const int gather_grid = (N_NODES * 32 + 255) / 256;   // 6250

    // layer 0: x -> gemm (f16 convert in prologue), writes msg buf A
    gemm_kernel<<<gemm_grid, 256, TC_SMEM>>>(x, 0, N_NODES, nullptr, nullptr, 1);
    // layers 1-4: gather(+bias/relu, fp16 agg) ; gemm -> msg buf
    for (int l = 1; l < 5; l++) {
        gather_kernel<<<gather_grid, 256>>>(l, b[l - 1]);
        gemm_kernel<<<gemm_grid, 256, TC_SMEM>>>(nullptr, l, N_NODES, nullptr, nullptr, 1);
    }
    // FC (layer 5): gather(+b4/relu) ; gemm -> relu(+bfc) pooled into g_pool
    gather_kernel<<<gather_grid, 256>>>(5, b[4]);
    gemm_kernel<<<gemm_grid, 256, TC_SMEM>>>(nullptr, 5, N_NODES, b[5], batch, 0);

    final_kernel<<<N_GRAPHS, 128>>>(Wlin, blin, out);
}

// round 16
// speedup vs baseline: 1.0574x; 1.0574x over previous
#include <cuda_runtime.h>
#include <cuda_fp16.h>
#include <cstdint>

#define N_NODES   50000
#define N_EDGES   600000
#define HID       128
#define N_GRAPHS  128
#define N_CLASSES 10

#define SCAN_B    512
#define SCAN_NB   ((N_NODES + SCAN_B - 1) / SCAN_B)    // 98

// ---------------- scratch (no allocation allowed) ----------------
__device__ __half g_aggH[(size_t)N_NODES * HID];  // fp16 GEMM input (activations)
__device__ __half g_hbA [(size_t)N_NODES * HID];  // fp16 messages, ping
__device__ __half g_hbB [(size_t)N_NODES * HID];  // fp16 messages, pong
__device__ float g_dinv[N_NODES];
__device__ int   g_deg [N_NODES];
__device__ int   g_cur [N_NODES];
__device__ int   g_rowptr[N_NODES + 1];
__device__ int   g_csr_src[N_EDGES];
__device__ int   g_bsum[SCAN_NB];
__device__ float g_pool[N_GRAPHS * HID];
__device__ float g_cnt [N_GRAPHS];
// W in mma.sync B-fragment layout, f16 hi/lo: [layer][term][kstep][ntile][lane]
__device__ uint2 g_Bfrag[6][2][8][16][32];

// ---------------- setup kernels ----------------
__global__ void zero_kernel() {
    int i = blockIdx.x * blockDim.x + threadIdx.x;
    if (i < N_NODES)      { g_deg[i] = 0; g_cur[i] = 0; }
    if (i < N_GRAPHS * HID) g_pool[i] = 0.f;
    if (i < N_GRAPHS)       g_cnt[i] = 0.f;
}

__global__ void deg_kernel(const int* __restrict__ ei) {
    int e = blockIdx.x * blockDim.x + threadIdx.x;
    if (e < N_EDGES) atomicAdd(&g_deg[ei[N_EDGES + e]], 1);
}

// dinv + graph node counts in one pass
__global__ void dinv_kernel(const int* __restrict__ batch) {
    int i = blockIdx.x * blockDim.x + threadIdx.x;
    if (i < N_NODES) {
        g_dinv[i] = rsqrtf((float)g_deg[i] + 1.0f);
        atomicAdd(&g_cnt[batch[i]], 1.f);
    }
}

// Build f16 hi/lo B fragments for all 6 layers in one launch.
struct WPtrs { const float* p[6]; };
__global__ void wprep_kernel(WPtrs wp) {
    int t = blockIdx.x * blockDim.x + threadIdx.x;   // 0..24575
    if (t >= 6 * 8 * 16 * 32) return;
    int l    = t >> 12;
    int s    = (t >> 9) & 7;
    int j    = (t >> 5) & 15;
    int lane = t & 31;
    const float* W = wp.p[l];
    int k0 = s * 16 + (lane & 3) * 2;
    int nn = j * 8 + (lane >> 2);
    unsigned hw[2], lw[2];
    #pragma unroll
    for (int q = 0; q < 2; q++) {
        float w0 = W[(k0 + q * 8)     * 128 + nn];
        float w1 = W[(k0 + q * 8 + 1) * 128 + nn];
        __half h0 = __float2half_rn(w0);
        __half h1 = __float2half_rn(w1);
        __half l0 = __float2half_rn(w0 - __half2float(h0));
        __half l1 = __float2half_rn(w1 - __half2float(h1));
        hw[q] = (unsigned)__half_as_ushort(h0)
              | ((unsigned)__half_as_ushort(h1) << 16);
        lw[q] = (unsigned)__half_as_ushort(l0)
              | ((unsigned)__half_as_ushort(l1) << 16);
    }
    g_Bfrag[l][0][s][j][lane] = make_uint2(hw[0], hw[1]);
    g_Bfrag[l][1][s][j][lane] = make_uint2(lw[0], lw[1]);
}

// ---- decoupled scan ----
__global__ __launch_bounds__(SCAN_B) void scan1_kernel() {
    __shared__ int s[SCAN_B];
    int i = blockIdx.x * SCAN_B + threadIdx.x;
    int v = (i < N_NODES) ? g_deg[i] : 0;
    s[threadIdx.x] = v;
    __syncthreads();
    #pragma unroll
    for (int off = 1; off < SCAN_B; off <<= 1) {
        int t = (threadIdx.x >= off) ? s[threadIdx.x - off] : 0;
        __syncthreads();
        s[threadIdx.x] += t;
        __syncthreads();
    }
    if (i < N_NODES) g_rowptr[i + 1] = s[threadIdx.x];
    if (threadIdx.x == SCAN_B - 1) g_bsum[blockIdx.x] = s[SCAN_B - 1];
}

__global__ void scan2_kernel() {
    __shared__ int s[128];
    int v = (threadIdx.x < SCAN_NB) ? g_bsum[threadIdx.x] : 0;
    s[threadIdx.x] = v;
    __syncthreads();
    #pragma unroll
    for (int off = 1; off < 128; off <<= 1) {
        int t = (threadIdx.x >= off) ? s[threadIdx.x - off] : 0;
        __syncthreads();
        s[threadIdx.x] += t;
        __syncthreads();
    }
    if (threadIdx.x < SCAN_NB) g_bsum[threadIdx.x] = s[threadIdx.x] - v;
}

__global__ void scan3_kernel() {
    int i = blockIdx.x * blockDim.x + threadIdx.x;
    if (i == 0) g_rowptr[0] = 0;
    if (i < N_NODES) g_rowptr[i + 1] += g_bsum[i / SCAN_B];
}

__global__ void place_kernel(const int* __restrict__ ei) {
    int e = blockIdx.x * blockDim.x + threadIdx.x;
    if (e >= N_EDGES) return;
    int r = ei[e];
    int c = ei[N_EDGES + e];
    int pos = g_rowptr[c] + atomicAdd(&g_cur[c], 1);
    g_csr_src[pos] = r;
}

// ---------------- gather: msgs -> relu(dinv*sum + bias) -> fp16 agg ------
__device__ __forceinline__ float4 h4_to_f4(uint2 u) {
    __half2 a = *(__half2*)&u.x;
    __half2 b = *(__half2*)&u.y;
    float2 fa = __half22float2(a);
    float2 fb = __half22float2(b);
    return make_float4(fa.x, fa.y, fb.x, fb.y);
}

__global__ __launch_bounds__(256) void gather_kernel(
    int layer, const float* __restrict__ bias)
{
    int gt   = blockIdx.x * blockDim.x + threadIdx.x;
    int node = gt >> 5;
    int lane = gt & 31;
    if (node >= N_NODES) return;

    const uint2* hb2 = (const uint2*)((layer & 1) ? g_hbA : g_hbB);
    float4 acc  = h4_to_f4(hb2[(size_t)node * 32 + lane]);   // self-loop
    float4 acc2 = make_float4(0.f, 0.f, 0.f, 0.f);
    int j  = g_rowptr[node];
    int e1 = g_rowptr[node + 1];

    for (; j + 8 <= e1; j += 8) {
        int s0 = g_csr_src[j];
        int s1 = g_csr_src[j + 1];
        int s2 = g_csr_src[j + 2];
        int s3 = g_csr_src[j + 3];
        int s4 = g_csr_src[j + 4];
        int s5 = g_csr_src[j + 5];
        int s6 = g_csr_src[j + 6];
        int s7 = g_csr_src[j + 7];
        float4 v0 = h4_to_f4(hb2[(size_t)s0 * 32 + lane]);
        float4 v1 = h4_to_f4(hb2[(size_t)s1 * 32 + lane]);
        float4 v2 = h4_to_f4(hb2[(size_t)s2 * 32 + lane]);
        float4 v3 = h4_to_f4(hb2[(size_t)s3 * 32 + lane]);
        float4 v4 = h4_to_f4(hb2[(size_t)s4 * 32 + lane]);
        float4 v5 = h4_to_f4(hb2[(size_t)s5 * 32 + lane]);
        float4 v6 = h4_to_f4(hb2[(size_t)s6 * 32 + lane]);
        float4 v7 = h4_to_f4(hb2[(size_t)s7 * 32 + lane]);
        acc.x  += (v0.x + v1.x) + (v2.x + v3.x);
        acc.y  += (v0.y + v1.y) + (v2.y + v3.y);
        acc.z  += (v0.z + v1.z) + (v2.z + v3.z);
        acc.w  += (v0.w + v1.w) + (v2.w + v3.w);
        acc2.x += (v4.x + v5.x) + (v6.x + v7.x);
        acc2.y += (v4.y + v5.y) + (v6.y + v7.y);
        acc2.z += (v4.z + v5.z) + (v6.z + v7.z);
        acc2.w += (v4.w + v5.w) + (v6.w + v7.w);
    }
    if (j + 4 <= e1) {
        int s0 = g_csr_src[j];
        int s1 = g_csr_src[j + 1];
        int s2 = g_csr_src[j + 2];
        int s3 = g_csr_src[j + 3];
        float4 v0 = h4_to_f4(hb2[(size_t)s0 * 32 + lane]);
        float4 v1 = h4_to_f4(hb2[(size_t)s1 * 32 + lane]);
        float4 v2 = h4_to_f4(hb2[(size_t)s2 * 32 + lane]);
        float4 v3 = h4_to_f4(hb2[(size_t)s3 * 32 + lane]);
        acc.x += (v0.x + v1.x) + (v2.x + v3.x);
        acc.y += (v0.y + v1.y) + (v2.y + v3.y);
        acc.z += (v0.z + v1.z) + (v2.z + v3.z);
        acc.w += (v0.w + v1.w) + (v2.w + v3.w);
        j += 4;
    }
    for (; j < e1; j++) {
        float4 v = h4_to_f4(hb2[(size_t)g_csr_src[j] * 32 + lane]);
        acc.x += v.x; acc.y += v.y; acc.z += v.z; acc.w += v.w;
    }
    acc.x += acc2.x; acc.y += acc2.y; acc.z += acc2.z; acc.w += acc2.w;
    float d = g_dinv[node];
    float4 pb = ((const float4*)bias)[lane];
    float4 a;
    a.x = fmaxf(fmaf(acc.x, d, pb.x), 0.f);
    a.y = fmaxf(fmaf(acc.y, d, pb.y), 0.f);
    a.z = fmaxf(fmaf(acc.z, d, pb.z), 0.f);
    a.w = fmaxf(fmaf(acc.w, d, pb.w), 0.f);
    __half2 o0 = __float22half2_rn(make_float2(a.x, a.y));
    __half2 o1 = __float22half2_rn(make_float2(a.z, a.w));
    uint2 o;
    o.x = *(unsigned*)&o0;
    o.y = *(unsigned*)&o1;
    ((uint2*)g_aggH)[(size_t)node * 32 + lane] = o;
}

// ---------------- mma.sync helper ----------------
__device__ __forceinline__ void mma_f16(float* d, const unsigned* a,
                                        const unsigned* b) {
    asm("mma.sync.aligned.m16n8k16.row.col.f32.f16.f16.f32 "
        "{%0,%1,%2,%3}, {%4,%5,%6,%7}, {%8,%9}, {%0,%1,%2,%3};"
        : "+f"(d[0]), "+f"(d[1]), "+f"(d[2]), "+f"(d[3])
        : "r"(a[0]), "r"(a[1]), "r"(a[2]), "r"(a[3]), "r"(b[0]), "r"(b[1]));
}

#define A_LD    136                          // padded f16 row stride
#define TC_SMEM (128 * A_LD * 2)             // 34816 B (8704 floats)
#define MAX_SPAN 68                          // pool staging capacity

// ---------------- conv GEMM (lean, R13 form + layer-0 X path) ------------
__global__ __launch_bounds__(256, 2) void gemm_conv_kernel(
    const float* __restrict__ X, int layer, int n)
{
    extern __shared__ char smem[];
    __half* aS = (__half*)smem;
    __half* hbOut = (layer & 1) ? g_hbB : g_hbA;

    int tid  = threadIdx.x;
    int lane = tid & 31;
    int wid  = tid >> 5;
    int row0 = blockIdx.x * 128;

    if (X) {
        #pragma unroll
        for (int it = 0; it < 32; it++) {
            int j = tid + it * 256;
            int r = j >> 6;
            int c = (j & 63) * 2;
            int row = row0 + r;
            float2 v = make_float2(0.f, 0.f);
            if (row < n) v = *(const float2*)&X[(size_t)row * HID + c];
            __half2 h = __float22half2_rn(v);
            *(unsigned*)&aS[r * A_LD + c] = *(unsigned*)&h;
        }
    } else {
        const uint4* src = (const uint4*)g_aggH;
        #pragma unroll
        for (int it = 0; it < 8; it++) {
            int j = tid + it * 256;
            int r = j >> 4;
            int q = j & 15;
            int row = row0 + r;
            uint4 v = make_uint4(0u, 0u, 0u, 0u);
            if (row < n) v = src[(size_t)row * 16 + q];
            *(uint4*)&aS[r * A_LD + q * 8] = v;
        }
    }
    __syncthreads();

    int wm = wid & 3;
    int wn = wid >> 2;
    int rA = wm * 32 + (lane >> 2);
    int cGrp = (lane & 3) * 2;

    float acc[2][8][4];
    #pragma unroll
    for (int i = 0; i < 2; i++)
        #pragma unroll
        for (int j = 0; j < 8; j++)
            #pragma unroll
            for (int q = 0; q < 4; q++) acc[i][j][q] = 0.f;

    const uint2* bfragHi = &g_Bfrag[layer][0][0][0][0];
    const uint2* bfragLo = &g_Bfrag[layer][1][0][0][0];

    #pragma unroll
    for (int s = 0; s < 8; s++) {
        int kc = s * 16 + cGrp;
        unsigned a[2][4];
        #pragma unroll
        for (int i = 0; i < 2; i++) {
            int r = rA + i * 16;
            a[i][0] = *(const unsigned*)&aS[(r    ) * A_LD + kc    ];
            a[i][1] = *(const unsigned*)&aS[(r + 8) * A_LD + kc    ];
            a[i][2] = *(const unsigned*)&aS[(r    ) * A_LD + kc + 8];
            a[i][3] = *(const unsigned*)&aS[(r + 8) * A_LD + kc + 8];
        }
        #pragma unroll
        for (int j = 0; j < 8; j++) {
            int nt = wn * 8 + j;
            uint2 bh = bfragHi[(s * 16 + nt) * 32 + lane];
            uint2 bl = bfragLo[(s * 16 + nt) * 32 + lane];
            #pragma unroll
            for (int i = 0; i < 2; i++) {
                mma_f16(acc[i][j], a[i], (const unsigned*)&bh);
                mma_f16(acc[i][j], a[i], (const unsigned*)&bl);
            }
        }
    }

    #pragma unroll
    for (int i = 0; i < 2; i++) {
        int r0 = row0 + rA + i * 16;
        int r1 = r0 + 8;
        bool ok0 = r0 < n, ok1 = r1 < n;
        float d0s = ok0 ? g_dinv[r0] : 0.f;
        float d1s = ok1 ? g_dinv[r1] : 0.f;
        #pragma unroll
        for (int j = 0; j < 8; j++) {
            int col = wn * 64 + j * 8 + cGrp;
            if (ok0) {
                __half2 o = __float22half2_rn(
                    make_float2(acc[i][j][0] * d0s, acc[i][j][1] * d0s));
                *(__half2*)&hbOut[(size_t)r0 * HID + col] = o;
            }
            if (ok1) {
                __half2 o = __float22half2_rn(
                    make_float2(acc[i][j][2] * d1s, acc[i][j][3] * d1s));
                *(__half2*)&hbOut[(size_t)r1 * HID + col] = o;
            }
        }
    }
}

// ---------------- FC GEMM with fused mean-pool accumulation --------------
__global__ __launch_bounds__(256, 2) void gemm_fc_kernel(
    int layer, int n, const float* __restrict__ postBias,
    const int* __restrict__ batch)
{
    extern __shared__ char smem[];
    __half* aS = (__half*)smem;

    int tid  = threadIdx.x;
    int lane = tid & 31;
    int wid  = tid >> 5;
    int row0 = blockIdx.x * 128;

    {
        const uint4* src = (const uint4*)g_aggH;
        #pragma unroll
        for (int it = 0; it < 8; it++) {
            int j = tid + it * 256;
            int r = j >> 4;
            int q = j & 15;
            int row = row0 + r;
            uint4 v = make_uint4(0u, 0u, 0u, 0u);
            if (row < n) v = src[(size_t)row * 16 + q];
            *(uint4*)&aS[r * A_LD + q * 8] = v;
        }
    }
    __syncthreads();

    int wm = wid & 3;
    int wn = wid >> 2;
    int rA = wm * 32 + (lane >> 2);
    int cGrp = (lane & 3) * 2;

    float acc[2][8][4];
    #pragma unroll
    for (int i = 0; i < 2; i++)
        #pragma unroll
        for (int j = 0; j < 8; j++)
            #pragma unroll
            for (int q = 0; q < 4; q++) acc[i][j][q] = 0.f;

    const uint2* bfragHi = &g_Bfrag[layer][0][0][0][0];
    const uint2* bfragLo = &g_Bfrag[layer][1][0][0][0];

    #pragma unroll
    for (int s = 0; s < 8; s++) {
        int kc = s * 16 + cGrp;
        unsigned a[2][4];
        #pragma unroll
        for (int i = 0; i < 2; i++) {
            int r = rA + i * 16;
            a[i][0] = *(const unsigned*)&aS[(r    ) * A_LD + kc    ];
            a[i][1] = *(const unsigned*)&aS[(r + 8) * A_LD + kc    ];
            a[i][2] = *(const unsigned*)&aS[(r    ) * A_LD + kc + 8];
            a[i][3] = *(const unsigned*)&aS[(r + 8) * A_LD + kc + 8];
        }
        #pragma unroll
        for (int j = 0; j < 8; j++) {
            int nt = wn * 8 + j;
            uint2 bh = bfragHi[(s * 16 + nt) * 32 + lane];
            uint2 bl = bfragLo[(s * 16 + nt) * 32 + lane];
            #pragma unroll
            for (int i = 0; i < 2; i++) {
                mma_f16(acc[i][j], a[i], (const unsigned*)&bh);
                mma_f16(acc[i][j], a[i], (const unsigned*)&bl);
            }
        }
    }

    // fused relu(+bias) + graph-mean-pool accumulation
    __syncthreads();                        // done with aS
    float* sp = (float*)smem;

    int rlast = min(row0 + 127, n - 1);
    int g0   = batch[row0];
    int span = batch[rlast] - g0 + 1;       // sorted batch

    bool useSmem = (span <= MAX_SPAN);
    if (useSmem) {
        for (int i2 = tid; i2 < span * 128; i2 += 256) sp[i2] = 0.f;
    }
    __syncthreads();

    int gl[4];
    #pragma unroll
    for (int k = 0; k < 4; k++) {
        int rr = row0 + rA + ((k >> 1) * 16) + ((k & 1) * 8);
        gl[k] = (rr < n) ? (batch[rr] - g0) : -1;
    }

    if (useSmem && gl[0] >= 0 && gl[0] == gl[1] && gl[0] == gl[2]
        && gl[0] == gl[3]) {
        float* dst = sp + gl[0] * 128;
        #pragma unroll
        for (int j = 0; j < 8; j++) {
            int col = wn * 64 + j * 8 + cGrp;
            float b0 = postBias[col], b1 = postBias[col + 1];
            float s0 = fmaxf(acc[0][j][0] + b0, 0.f)
                     + fmaxf(acc[0][j][2] + b0, 0.f)
                     + fmaxf(acc[1][j][0] + b0, 0.f)
                     + fmaxf(acc[1][j][2] + b0, 0.f);
            float s1 = fmaxf(acc[0][j][1] + b1, 0.f)
                     + fmaxf(acc[0][j][3] + b1, 0.f)
                     + fmaxf(acc[1][j][1] + b1, 0.f)
                     + fmaxf(acc[1][j][3] + b1, 0.f);
            atomicAdd(dst + col,     s0);
            atomicAdd(dst + col + 1, s1);
        }
    } else {
        #pragma unroll
        for (int k = 0; k < 4; k++) {
            if (gl[k] < 0) continue;
            int i  = k >> 1;
            int qb = (k & 1) * 2;
            #pragma unroll
            for (int j = 0; j < 8; j++) {
                int col = wn * 64 + j * 8 + cGrp;
                float v0 = fmaxf(acc[i][j][qb]     + postBias[col],     0.f);
                float v1 = fmaxf(acc[i][j][qb + 1] + postBias[col + 1], 0.f);
                if (useSmem) {
                    atomicAdd(sp + gl[k] * 128 + col,     v0);
                    atomicAdd(sp + gl[k] * 128 + col + 1, v1);
                } else {
                    atomicAdd(&g_pool[(g0 + gl[k]) * 128 + col],     v0);
                    atomicAdd(&g_pool[(g0 + gl[k]) * 128 + col + 1], v1);
                }
            }
        }
    }
    __syncthreads();
    if (useSmem) {
        for (int i2 = tid; i2 < span * 128; i2 += 256) {
            float v = sp[i2];
            if (v != 0.f)
                atomicAdd(&g_pool[(g0 + (i2 >> 7)) * 128 + (i2 & 127)], v);
        }
    }
}

// ---------------- final head: mean, embeddings out, logits ----------------
__global__ void final_kernel(const float* __restrict__ Wlin,
                             const float* __restrict__ blin,
                             float* __restrict__ out) {
    int g = blockIdx.x;
    int t = threadIdx.x;
    __shared__ float p[HID];
    float c = fmaxf(g_cnt[g], 1.0f);
    float v = g_pool[g * HID + t] / c;
    out[N_GRAPHS * N_CLASSES + g * HID + t] = v;
    p[t] = v;
    __syncthreads();
    if (t < N_CLASSES) {
        float s = blin[t];
        #pragma unroll 8
        for (int j = 0; j < HID; j++) s += p[j] * Wlin[j * N_CLASSES + t];
        out[g * N_CLASSES + t] = s;
    }
}

// ---------------- launch ----------------
extern "C" void kernel_launch(void* const* d_in, const int* in_sizes, int n_in,
                              void* d_out, int out_size)
{
    const float* x     = (const float*)d_in[0];
    const int*   ei    = (const int*)d_in[1];      // int32 (JAX x64 disabled)
    const int*   batch = (const int*)d_in[2];
    const float* W[6] = {(const float*)d_in[3],  (const float*)d_in[5],
                         (const float*)d_in[7],  (const float*)d_in[9],
                         (const float*)d_in[11], (const float*)d_in[13]};
    const float* b[6] = {(const float*)d_in[4],  (const float*)d_in[6],
                         (const float*)d_in[8],  (const float*)d_in[10],
                         (const float*)d_in[12], (const float*)d_in[14]};
    const float* Wlin = (const float*)d_in[15];
    const float* blin = (const float*)d_in[16];
    float* out = (float*)d_out;

    cudaFuncSetAttribute(gemm_conv_kernel,
                         cudaFuncAttributeMaxDynamicSharedMemorySize, TC_SMEM);
    cudaFuncSetAttribute(gemm_fc_kernel,
                         cudaFuncAttributeMaxDynamicSharedMemorySize, TC_SMEM);

    zero_kernel <<<(N_NODES + 255) / 256, 256>>>();
    deg_kernel  <<<(N_EDGES + 255) / 256, 256>>>(ei);
    dinv_kernel <<<(N_NODES + 255) / 256, 256>>>(batch);
    scan1_kernel<<<SCAN_NB, SCAN_B>>>();
    scan2_kernel<<<1, 128>>>();
    scan3_kernel<<<(N_NODES + 255) / 256, 256>>>();
    place_kernel<<<(N_EDGES + 255) / 256, 256>>>(ei);
    WPtrs wp;
    for (int l = 0; l < 6; l++) wp.p[l] = W[l];
    wprep_kernel<<<96, 256>>>(wp);

    const int gemm_grid   = (N_NODES + 127) / 128;        // 391
    const int gather_grid = (N_NODES * 32 + 255) / 256;   // 6250

    // layer 0: x -> conv gemm (f16 convert in prologue), writes msg buf A
    gemm_conv_kernel<<<gemm_grid, 256, TC_SMEM>>>(x, 0, N_NODES);
    // layers 1-4: gather(+bias/relu, fp16 agg) ; conv gemm -> msg buf
    for (int l = 1; l < 5; l++) {
        gather_kernel<<<gather_grid, 256>>>(l, b[l - 1]);
        gemm_conv_kernel<<<gemm_grid, 256, TC_SMEM>>>(nullptr, l, N_NODES);
    }
    // FC (layer 5): gather(+b4/relu) ; FC gemm -> relu(+bfc) pooled into g_pool
    gather_kernel<<<gather_grid, 256>>>(5, b[4]);
    gemm_fc_kernel<<<gemm_grid, 256, TC_SMEM>>>(5, N_NODES, b[5], batch);

    final_kernel<<<N_GRAPHS, 128>>>(Wlin, blin, out);
}